// round 8
// baseline (speedup 1.0000x reference)
#include <cuda_runtime.h>
#include <cstdint>

typedef unsigned long long ull;

#define N_NODES 100000
#define N_EDGES 1600000
#define D 64
#define SCAN_BLOCKS 98   // ceil(100000/1024)

// Scratch (no cudaMalloc allowed).
__device__ float g_dinv[N_NODES];
__device__ float g_xw1[N_NODES * D];
__device__ int   g_cnt[N_NODES];
__device__ int   g_offs[N_NODES + 1];
__device__ int   g_cursor[N_NODES];
__device__ int2  g_srt[N_EDGES];
__device__ int   g_bsum[SCAN_BLOCKS];
__device__ int   g_idx64;

__device__ __forceinline__ int load_idx(const long long* ei64,
                                        const int* ei32, int is64,
                                        long long pos) {
    return is64 ? (int)ei64[pos] : ei32[pos];
}

// ---------------------------------------------------------------------------
// K0: zero deg + cnt; thread 0 detects edge_index dtype (int64 indices < 2^31
// LE have every odd 32-bit word == 0).
__global__ void k_init(const int* __restrict__ ei32) {
    int i = blockIdx.x * blockDim.x + threadIdx.x;
    if (i < N_NODES) {
        g_dinv[i] = 0.0f;
        g_cnt[i] = 0;
    }
    if (i == 0) {
        int all_zero = 1;
        for (int j = 1; j < 128; j += 2)
            if (ei32[j] != 0) all_zero = 0;
        g_idx64 = all_zero;
    }
}

// K1: single edge pass: deg[row] += w  and  cnt[col] += 1
__global__ __launch_bounds__(256) void k_edge1(const long long* __restrict__ ei64,
                                               const int* __restrict__ ei32,
                                               const float* __restrict__ w) {
    int e = blockIdx.x * blockDim.x + threadIdx.x;
    if (e >= N_EDGES) return;
    int is64 = g_idx64;
    int row = load_idx(ei64, ei32, is64, e);
    int col = load_idx(ei64, ei32, is64, (long long)e + N_EDGES);
    if ((unsigned)row < N_NODES) atomicAdd(&g_dinv[row], w[e]);
    if ((unsigned)col < N_NODES) atomicAdd(&g_cnt[col], 1);
}

// ---------------------------------------------------------------------------
// Scan step 1: per-block sums of cnt (1024 elems per block). Also finalizes
// dinv = deg > 0 ? rsqrt(deg) : 0 (folded in; same index range).
__global__ __launch_bounds__(1024) void k_scan1() {
    __shared__ int sh[1024];
    int t = threadIdx.x;
    int i = blockIdx.x * 1024 + t;
    if (i < N_NODES) {
        float d = g_dinv[i];
        g_dinv[i] = (d > 0.0f) ? rsqrtf(d) : 0.0f;
    }
    sh[t] = (i < N_NODES) ? g_cnt[i] : 0;
    __syncthreads();
    for (int s = 512; s > 0; s >>= 1) {
        if (t < s) sh[t] += sh[t + s];
        __syncthreads();
    }
    if (t == 0) g_bsum[blockIdx.x] = sh[0];
}

// Scan step 2: exclusive scan of block sums.
__global__ void k_scan2() {
    __shared__ int sh[SCAN_BLOCKS];
    int t = threadIdx.x;
    if (t < SCAN_BLOCKS) sh[t] = g_bsum[t];
    __syncthreads();
    if (t == 0) {
        int run = 0;
        for (int j = 0; j < SCAN_BLOCKS; j++) {
            int v = sh[j];
            g_bsum[j] = run;
            run += v;
        }
        g_offs[N_NODES] = run;
    }
}

// Scan step 3: per-block inclusive scan -> exclusive offsets + cursor copy.
__global__ __launch_bounds__(1024) void k_scan3() {
    __shared__ int sh[1024];
    int t = threadIdx.x;
    int i = blockIdx.x * 1024 + t;
    int own = (i < N_NODES) ? g_cnt[i] : 0;
    sh[t] = own;
    __syncthreads();
    for (int s = 1; s < 1024; s <<= 1) {
        int v = (t >= s) ? sh[t - s] : 0;
        __syncthreads();
        sh[t] += v;
        __syncthreads();
    }
    if (i < N_NODES) {
        int excl = sh[t] - own + g_bsum[blockIdx.x];
        g_offs[i] = excl;
        g_cursor[i] = excl;
    }
}

// K-place: bucket each edge into its col segment; precompute norm.
__global__ __launch_bounds__(256) void k_place(const long long* __restrict__ ei64,
                                               const int* __restrict__ ei32,
                                               const float* __restrict__ w) {
    int e = blockIdx.x * blockDim.x + threadIdx.x;
    if (e >= N_EDGES) return;
    int is64 = g_idx64;
    int row = load_idx(ei64, ei32, is64, e);
    int col = load_idx(ei64, ei32, is64, (long long)e + N_EDGES);
    if ((unsigned)row >= N_NODES || (unsigned)col >= N_NODES) return;
    float norm = -g_dinv[row] * w[e] * g_dinv[col];
    int pos = atomicAdd(&g_cursor[col], 1);
    g_srt[pos] = make_int2(row, __float_as_int(norm));
}

// ---------------------------------------------------------------------------
// K-gemm: out = x @ W0 + b ;  g_xw1 = x @ W1
// 128 threads: mat = t>>6 (W0 vs W1), node-in-tile ng = (t>>5)&1,
// column pair cp = t&31 (cols 2cp, 2cp+1).
// Weights live in 64 packed f32x2 REGISTERS per thread (loaded once per
// block, reused over all tiles). x is staged in smem pre-duplicated (xv,xv)
// so the inner loop is exactly: LDS.64 + fma.rn.f32x2 per k.
__global__ __launch_bounds__(128) void k_gemm(const float* __restrict__ x,
                                              const float* __restrict__ W0,
                                              const float* __restrict__ W1,
                                              const float* __restrict__ b,
                                              float* __restrict__ out) {
    __shared__ ull sx2[2][D];

    int t   = threadIdx.x;
    int cp  = t & 31;
    int ng  = (t >> 5) & 1;
    int mat = t >> 6;

    const ull* Wp = reinterpret_cast<const ull*>(mat ? W1 : W0);
    ull wreg[D];
#pragma unroll
    for (int k = 0; k < D; k++) wreg[k] = Wp[k * 32 + cp];

    float2 bias = make_float2(0.0f, 0.0f);
    if (mat == 0) bias = reinterpret_cast<const float2*>(b)[cp];

    int nw = t >> 6;     // writer node (0/1)
    int kw = t & 63;     // writer k

    const int ntiles = N_NODES / 2;   // 100000 % 2 == 0
    for (int tile = blockIdx.x; tile < ntiles; tile += gridDim.x) {
        float xv = x[(tile * 2 + nw) * D + kw];
        unsigned xb = __float_as_uint(xv);
        sx2[nw][kw] = ((ull)xb << 32) | (ull)xb;
        __syncthreads();

        ull acc0 = 0, acc1 = 0;   // packed (0.f, 0.f)
#pragma unroll
        for (int k = 0; k < D; k += 2) {
            asm("fma.rn.f32x2 %0, %1, %2, %0;"
                : "+l"(acc0) : "l"(sx2[ng][k]),     "l"(wreg[k]));
            asm("fma.rn.f32x2 %0, %1, %2, %0;"
                : "+l"(acc1) : "l"(sx2[ng][k + 1]), "l"(wreg[k + 1]));
        }
        ull acc;
        asm("add.rn.f32x2 %0, %1, %2;" : "=l"(acc) : "l"(acc0), "l"(acc1));
        float lo = __uint_as_float((unsigned)acc);
        float hi = __uint_as_float((unsigned)(acc >> 32));

        int node = tile * 2 + ng;
        if (mat == 0) {
            reinterpret_cast<float2*>(out)[node * 32 + cp] =
                make_float2(lo + bias.x, hi + bias.y);
        } else {
            reinterpret_cast<float2*>(g_xw1)[node * 32 + cp] =
                make_float2(lo, hi);
        }
        __syncthreads();
    }
}

// ---------------------------------------------------------------------------
// K-spmm: one warp per destination column; no atomics.
// srt stream software-pipelined 2-deep so the gather never waits on the
// same-iteration srt load.
__global__ __launch_bounds__(256) void k_spmm(float* __restrict__ out) {
    int gw = (blockIdx.x * blockDim.x + threadIdx.x) >> 5;
    if (gw >= N_NODES) return;
    int lane = threadIdx.x & 31;

    int start = g_offs[gw];
    int end   = g_offs[gw + 1];

    int2 a0 = make_int2(0, 0), a1 = make_int2(0, 0);
    if (start < end)     a0 = __ldg(&g_srt[start]);
    if (start + 1 < end) a1 = __ldg(&g_srt[start + 1]);

    float ax = 0.0f, ay = 0.0f;
    for (int i = start; i < end; i++) {
        int2 cur = a0;
        a0 = a1;
        if (i + 2 < end) a1 = __ldg(&g_srt[i + 2]);

        float norm = __int_as_float(cur.y);
        const float2 v =
            *reinterpret_cast<const float2*>(&g_xw1[cur.x * D + lane * 2]);
        ax = fmaf(norm, v.x, ax);
        ay = fmaf(norm, v.y, ay);
    }

    float2* o = reinterpret_cast<float2*>(&out[gw * D + lane * 2]);
    float2 curo = *o;
    curo.x += ax;
    curo.y += ay;
    *o = curo;
}

// ---------------------------------------------------------------------------
extern "C" void kernel_launch(void* const* d_in, const int* in_sizes, int n_in,
                              void* d_out, int out_size) {
    // Bind inputs by element count (unambiguous for this problem).
    const float* x  = nullptr;
    const void*  ei = nullptr;
    const float* w  = nullptr;
    const float* W0 = nullptr;
    const float* W1 = nullptr;
    const float* b  = nullptr;
    for (int i = 0; i < n_in; i++) {
        long long n = in_sizes[i];
        if (n == (long long)N_NODES * D)      x  = (const float*)d_in[i];
        else if (n == 2LL * N_EDGES)          ei = d_in[i];
        else if (n == (long long)N_EDGES)     w  = (const float*)d_in[i];
        else if (n == D * D) { if (!W0) W0 = (const float*)d_in[i];
                               else     W1 = (const float*)d_in[i]; }
        else if (n == D)                      b  = (const float*)d_in[i];
    }
    const long long* ei64 = (const long long*)ei;
    const int*       ei32 = (const int*)ei;
    float* out = (float*)d_out;

    k_init<<<(N_NODES + 255) / 256, 256>>>(ei32);
    k_edge1<<<(N_EDGES + 255) / 256, 256>>>(ei64, ei32, w);
    k_scan1<<<SCAN_BLOCKS, 1024>>>();
    k_scan2<<<1, 128>>>();
    k_scan3<<<SCAN_BLOCKS, 1024>>>();
    k_place<<<(N_EDGES + 255) / 256, 256>>>(ei64, ei32, w);
    k_gemm<<<444, 128>>>(x, W0, W1, b, out);

    // one warp per column
    k_spmm<<<(N_NODES * 32 + 255) / 256, 256>>>(out);
}